// round 14
// baseline (speedup 1.0000x reference)
#include <cuda_runtime.h>
#include <cuda_fp16.h>
#include <math.h>
#include <float.h>
#include <cstdint>

// Problem constants
#define T_SEQ 2048
#define HID   4096
#define NH    16
#define DH    256
#define QKV_N (3 * NH * DH)      // 12288
#define Q_SIZE (NH * DH)         // 4096
#define EPS   1e-6f
#define LN_THETA 9.210340371976184f   // ln(10000)

// GEMM tile config (fp16 engine): CTA 128x128, warp 32x64, 8 warps, BK=64
#define BM 128
#define BN 128
#define BK 64
#define STRIDE 72
#define STAGES 3
#define STAGE_BYTES ((BM + BN) * STRIDE * 2)   // 36864
#define SMEM_BYTES (STAGES * STAGE_BYTES)      // 110592

// Flash v5: q-tile 64, kv-tile 32, 4 warps, FULL D=256, K/V double-buffered,
// V row-major via ldmatrix.trans. 2 CTAs/SM.
#define FQM 64
#define FKV 32
#define QSTR 264                   // 256 + 8 pad (halfs)
#define FOFF_K0 (FQM * QSTR * 2)               // 33792
#define FK_BYTES (FKV * QSTR * 2)              // 16896
#define FOFF_V0 (FOFF_K0 + 2 * FK_BYTES)       // 67584
#define FV_BYTES (FKV * QSTR * 2)              // 16896
#define FLASH_SMEM (FOFF_V0 + 2 * FV_BYTES)    // 101376

// ---------------------------------------------------------------------------
// Scratch (static device globals)
// ---------------------------------------------------------------------------
__device__ __half g_hidden_h[(size_t)T_SEQ * HID];
__device__ __half g_wqkv_h[(size_t)QKV_N * HID];
__device__ __half g_wo_h[(size_t)HID * Q_SIZE];
__device__ float  g_qkv[(size_t)T_SEQ * QKV_N];
__device__ __half g_qh[(size_t)T_SEQ * NH * DH];
__device__ __half g_kh[(size_t)T_SEQ * NH * DH];
__device__ __half g_vh[(size_t)T_SEQ * NH * DH];
__device__ __half g_attn_h[(size_t)T_SEQ * NH * DH];

// ---------------------------------------------------------------------------
// PTX helpers
// ---------------------------------------------------------------------------
__device__ __forceinline__ uint32_t smem_u32(const void* p) {
    uint32_t a;
    asm("{ .reg .u64 t; cvta.to.shared.u64 t, %1; cvt.u32.u64 %0, t; }" : "=r"(a) : "l"(p));
    return a;
}
#define CP_ASYNC16(dst, src) \
    asm volatile("cp.async.cg.shared.global [%0], [%1], 16;" :: "r"(dst), "l"(src))
#define CP_COMMIT() asm volatile("cp.async.commit_group;" ::: "memory")
#define CP_WAIT(n)  asm volatile("cp.async.wait_group %0;" :: "n"(n) : "memory")

__device__ __forceinline__ void ldmx4(uint32_t* r, uint32_t addr) {
    asm volatile("ldmatrix.sync.aligned.m8n8.x4.shared.b16 {%0,%1,%2,%3}, [%4];"
        : "=r"(r[0]), "=r"(r[1]), "=r"(r[2]), "=r"(r[3]) : "r"(addr));
}
__device__ __forceinline__ void ldmx4_trans(uint32_t* r, uint32_t addr) {
    asm volatile("ldmatrix.sync.aligned.m8n8.x4.trans.shared.b16 {%0,%1,%2,%3}, [%4];"
        : "=r"(r[0]), "=r"(r[1]), "=r"(r[2]), "=r"(r[3]) : "r"(addr));
}
__device__ __forceinline__ void mma_f16(float* d, const uint32_t* a, const uint32_t* b) {
    asm volatile(
        "mma.sync.aligned.m16n8k16.row.col.f32.f16.f16.f32 "
        "{%0,%1,%2,%3}, {%4,%5,%6,%7}, {%8,%9}, {%0,%1,%2,%3};"
        : "+f"(d[0]), "+f"(d[1]), "+f"(d[2]), "+f"(d[3])
        : "r"(a[0]), "r"(a[1]), "r"(a[2]), "r"(a[3]), "r"(b[0]), "r"(b[1]));
}
__device__ __forceinline__ uint32_t h2pack(float a, float b) {
    __half2 h = __floats2half2_rn(a, b);
    return *(uint32_t*)&h;
}

// ---------------------------------------------------------------------------
// fp16 mma.sync GEMM (unchanged from R8)
// ---------------------------------------------------------------------------
template<bool CSKIP, bool CKLIM, bool HALF_OUT>
__global__ __launch_bounds__(256, 2)
void h_gemm(const __half* __restrict__ A, const __half* __restrict__ B, void* __restrict__ Cv,
            int M, int N, int K, int lda, int ldb, int ldc,
            long long bA, long long bB, long long bC)
{
    const int row0 = blockIdx.y * BM;
    const int col0 = blockIdx.x * BN;
    if (CSKIP && col0 >= row0 + BM) return;
    const int Keff = CKLIM ? min(K, row0 + BM) : K;
    const int nCh = Keff / BK;

    A += (long long)blockIdx.z * bA;
    B += (long long)blockIdx.z * bB;

    extern __shared__ char smem[];
    const uint32_t sbase = smem_u32(smem);

    const int tid = threadIdx.x;
    const int wid = tid >> 5, lane = tid & 31;
    const int g = lane >> 2, t4 = lane & 3;
    const int warpM = (wid & 3) * 32;
    const int warpN = (wid >> 2) * 64;
    const int lrow = lane & 7, lsel = lane >> 3;

    const uint32_t aoff = ((warpM + (lsel & 1) * 8 + lrow) * STRIDE + (lsel >> 1) * 8) * 2;
    const uint32_t boff = ((warpN + (lsel >> 1) * 8 + lrow) * STRIDE + (lsel & 1) * 8) * 2;

    float acc[2][8][4];
    #pragma unroll
    for (int i = 0; i < 2; i++)
        #pragma unroll
        for (int j = 0; j < 8; j++)
            #pragma unroll
            for (int q = 0; q < 4; q++) acc[i][j][q] = 0.0f;

    auto load_stage = [&](int st, int ch) {
        const uint32_t sA = sbase + st * STAGE_BYTES;
        const uint32_t sB = sA + BM * STRIDE * 2;
        const int k0 = ch * BK;
        #pragma unroll
        for (int i = 0; i < 4; i++) {
            int u = tid + i * 256;
            int r = u >> 3, cu = u & 7;
            CP_ASYNC16(sA + (r * STRIDE + cu * 8) * 2,
                       &A[(size_t)(row0 + r) * lda + k0 + cu * 8]);
        }
        #pragma unroll
        for (int i = 0; i < 4; i++) {
            int u = tid + i * 256;
            int r = u >> 3, cu = u & 7;
            CP_ASYNC16(sB + (r * STRIDE + cu * 8) * 2,
                       &B[(size_t)(col0 + r) * ldb + k0 + cu * 8]);
        }
    };

    auto compute_k16 = [&](uint32_t sA, uint32_t sB, int kk) {
        uint32_t a[2][4];
        ldmx4(a[0], sA + aoff + kk * 32);
        ldmx4(a[1], sA + aoff + 16 * STRIDE * 2 + kk * 32);
        uint32_t b[8][2];
        #pragma unroll
        for (int j = 0; j < 4; ++j) {
            uint32_t r[4];
            ldmx4(r, sB + boff + j * 16 * STRIDE * 2 + kk * 32);
            b[2 * j][0] = r[0]; b[2 * j][1] = r[1];
            b[2 * j + 1][0] = r[2]; b[2 * j + 1][1] = r[3];
        }
        #pragma unroll
        for (int nt = 0; nt < 8; ++nt) {
            mma_f16(acc[0][nt], a[0], b[nt]);
            mma_f16(acc[1][nt], a[1], b[nt]);
        }
    };

    #pragma unroll
    for (int p = 0; p < STAGES - 1; ++p) {
        if (p < nCh) load_stage(p, p);
        CP_COMMIT();
    }

    for (int c = 0; c < nCh; ++c) {
        CP_WAIT(STAGES - 2);
        __syncthreads();

        const uint32_t sA = sbase + (c % STAGES) * STAGE_BYTES;
        const uint32_t sB = sA + BM * STRIDE * 2;

        compute_k16(sA, sB, 0);
        if (c + STAGES - 1 < nCh) load_stage((c + STAGES - 1) % STAGES, c + STAGES - 1);
        CP_COMMIT();
        #pragma unroll
        for (int kk = 1; kk < 4; ++kk)
            compute_k16(sA, sB, kk);
    }

    #pragma unroll
    for (int mt = 0; mt < 2; mt++) {
        const int r0 = row0 + warpM + mt * 16 + g;
        #pragma unroll
        for (int nt = 0; nt < 8; nt++) {
            const int cc = col0 + warpN + nt * 8 + t4 * 2;
            if (HALF_OUT) {
                __half* C = (__half*)Cv + (long long)blockIdx.z * bC;
                *(__half2*)&C[(size_t)r0 * ldc + cc] =
                    __floats2half2_rn(acc[mt][nt][0], acc[mt][nt][1]);
                *(__half2*)&C[(size_t)(r0 + 8) * ldc + cc] =
                    __floats2half2_rn(acc[mt][nt][2], acc[mt][nt][3]);
            } else {
                float* C = (float*)Cv + (long long)blockIdx.z * bC;
                *(float2*)&C[(size_t)r0 * ldc + cc]       = make_float2(acc[mt][nt][0], acc[mt][nt][1]);
                *(float2*)&C[(size_t)(r0 + 8) * ldc + cc] = make_float2(acc[mt][nt][2], acc[mt][nt][3]);
            }
        }
    }
}

// ---------------------------------------------------------------------------
// Flash v5: q-tile 64 (4 warps), kv-tile 32, register-P, FULL D=256,
// V via ldmatrix.trans, 2 CTAs/SM. Warp w owns rows w*16..w*16+15.
// ---------------------------------------------------------------------------
__global__ __launch_bounds__(128, 2)
void flash_kernel(const __half* __restrict__ Qg, const __half* __restrict__ Kg,
                  const __half* __restrict__ Vg, __half* __restrict__ Og)
{
    const int qtile = gridDim.x - 1 - blockIdx.x;   // longest work first
    const int q0 = qtile * FQM;
    const int h  = blockIdx.y;

    extern __shared__ char sm[];
    const uint32_t sb = smem_u32(sm);
    const uint32_t Qs = sb;

    const int tid = threadIdx.x;
    const int w = tid >> 5, lane = tid & 31;
    const int g = lane >> 2, t4 = lane & 3;
    const int lrow = lane & 7, lsel = lane >> 3;

    const __half* Qp = Qg + (size_t)h * DH;
    const __half* Kp = Kg + (size_t)h * DH;
    const __half* Vp = Vg + (size_t)h * DH;

    // Q tile (64 x 256): 2048 16B-units, 16 per thread
    #pragma unroll
    for (int i = 0; i < 16; i++) {
        int u = tid + i * 128;
        int r = u >> 5, cu = u & 31;
        CP_ASYNC16(Qs + (r * QSTR + cu * 8) * 2, Qp + (size_t)(q0 + r) * Q_SIZE + cu * 8);
    }

    auto load_kv = [&](int buf, int kv0) {
        const uint32_t Ks = sb + FOFF_K0 + buf * FK_BYTES;
        const uint32_t Vs = sb + FOFF_V0 + buf * FV_BYTES;
        #pragma unroll
        for (int i = 0; i < 8; i++) {           // K: 32 rows x 256 halfs
            int u = tid + i * 128;
            int r = u >> 5, cu = u & 31;
            CP_ASYNC16(Ks + (r * QSTR + cu * 8) * 2, Kp + (size_t)(kv0 + r) * Q_SIZE + cu * 8);
        }
        #pragma unroll
        for (int i = 0; i < 8; i++) {           // V: 32 rows x 256 halfs (row-major)
            int u = tid + i * 128;
            int r = u >> 5, cu = u & 31;
            CP_ASYNC16(Vs + (r * QSTR + cu * 8) * 2, Vp + (size_t)(kv0 + r) * Q_SIZE + cu * 8);
        }
    };

    const uint32_t aoffQ = ((w * 16 + (lsel & 1) * 8 + lrow) * QSTR + (lsel >> 1) * 8) * 2;
    const uint32_t boffK = (((lsel >> 1) * 8 + lrow) * QSTR + (lsel & 1) * 8) * 2;
    // trans-V: lane L -> V row (lsel&1)*8 + lrow, d col (lsel>>1)*8
    const uint32_t boffV = (((lsel & 1) * 8 + lrow) * QSTR + (lsel >> 1) * 8) * 2;

    float m0 = -1e30f, m1 = -1e30f, l0 = 0.0f, l1 = 0.0f;
    float o[32][4];
    #pragma unroll
    for (int i = 0; i < 32; i++)
        #pragma unroll
        for (int q = 0; q < 4; q++) o[i][q] = 0.0f;

    const int nkv = 2 * (qtile + 1);           // (q0 + FQM) / FKV
    load_kv(0, 0);                  // prologue: Q + KV(0) in one group
    CP_COMMIT();

    for (int it = 0; it < nkv; ++it) {
        const int kv0 = it * FKV;
        CP_WAIT(0);                 // current buffer (and Q on it=0) resident
        __syncthreads();            // everyone done reading buf (it+1)&1 from iter it-1
        if (it + 1 < nkv) load_kv((it + 1) & 1, kv0 + FKV);
        CP_COMMIT();                // overlaps with compute below

        const uint32_t Ks = sb + FOFF_K0 + (it & 1) * FK_BYTES;
        const uint32_t Vs = sb + FOFF_V0 + (it & 1) * FV_BYTES;

        // warp fully above the diagonal? skip (no barriers inside body)
        if (kv0 > q0 + w * 16 + 15) continue;

        // S = Q K^T  (16 q rows x 32 kv cols per warp)
        float s[4][4];
        #pragma unroll
        for (int i = 0; i < 4; i++)
            #pragma unroll
            for (int q = 0; q < 4; q++) s[i][q] = 0.0f;
        #pragma unroll
        for (int ks = 0; ks < 16; ++ks) {
            uint32_t a[4];
            ldmx4(a, Qs + aoffQ + ks * 32);
            #pragma unroll
            for (int j = 0; j < 2; ++j) {
                uint32_t r4[4];
                ldmx4(r4, Ks + boffK + j * 16 * QSTR * 2 + ks * 32);
                mma_f16(s[2 * j], a, r4);
                mma_f16(s[2 * j + 1], a, r4 + 2);
            }
        }

        // causal mask if this tile can cross the diagonal for this warp
        if (kv0 + FKV - 1 > q0 + w * 16) {
            const int rowg = q0 + w * 16 + g;
            #pragma unroll
            for (int nt = 0; nt < 4; ++nt) {
                const int col = kv0 + nt * 8 + t4 * 2;
                if (col     > rowg)     s[nt][0] = -1e30f;
                if (col + 1 > rowg)     s[nt][1] = -1e30f;
                if (col     > rowg + 8) s[nt][2] = -1e30f;
                if (col + 1 > rowg + 8) s[nt][3] = -1e30f;
            }
        }

        // online softmax, rows g (r=0) and g+8 (r=1)
        #pragma unroll
        for (int r = 0; r < 2; ++r) {
            float mx = -1e30f;
            #pragma unroll
            for (int nt = 0; nt < 4; ++nt)
                mx = fmaxf(mx, fmaxf(s[nt][2 * r], s[nt][2 * r + 1]));
            mx = fmaxf(mx, __shfl_xor_sync(0xffffffffu, mx, 1));
            mx = fmaxf(mx, __shfl_xor_sync(0xffffffffu, mx, 2));
            const float mold = r ? m1 : m0;
            const float mnew = fmaxf(mold, mx);
            float sum = 0.0f;
            #pragma unroll
            for (int nt = 0; nt < 4; ++nt) {
                float p0 = __expf(s[nt][2 * r] - mnew);
                float p1 = __expf(s[nt][2 * r + 1] - mnew);
                s[nt][2 * r] = p0; s[nt][2 * r + 1] = p1;
                sum += p0 + p1;
            }
            sum += __shfl_xor_sync(0xffffffffu, sum, 1);
            sum += __shfl_xor_sync(0xffffffffu, sum, 2);
            if (mnew > mold) {      // sc < 1: rescale needed (else sc==1.0 exactly)
                const float sc = __expf(mold - mnew);
                if (r == 0) { l0 = l0 * sc + sum; m0 = mnew; }
                else        { l1 = l1 * sc + sum; m1 = mnew; }
                #pragma unroll
                for (int nt = 0; nt < 32; ++nt) {
                    o[nt][2 * r]     *= sc;
                    o[nt][2 * r + 1] *= sc;
                }
            } else {
                if (r == 0) l0 += sum;
                else        l1 += sum;
            }
        }

        // O += P V with P straight from S registers; V^T frags via ldmatrix.trans
        #pragma unroll
        for (int ks2 = 0; ks2 < 2; ++ks2) {
            uint32_t a[4];
            a[0] = h2pack(s[2 * ks2][0],     s[2 * ks2][1]);
            a[1] = h2pack(s[2 * ks2][2],     s[2 * ks2][3]);
            a[2] = h2pack(s[2 * ks2 + 1][0], s[2 * ks2 + 1][1]);
            a[3] = h2pack(s[2 * ks2 + 1][2], s[2 * ks2 + 1][3]);
            const uint32_t vrow = Vs + boffV + ks2 * 16 * QSTR * 2;
            #pragma unroll
            for (int j = 0; j < 16; ++j) {      // full 256 d cols
                uint32_t r4[4];
                ldmx4_trans(r4, vrow + j * 32);
                mma_f16(o[2 * j], a, r4);
                mma_f16(o[2 * j + 1], a, r4 + 2);
            }
        }
    }

    const float i0 = 1.0f / l0, i1 = 1.0f / l1;
    const int tg = q0 + w * 16 + g;
    #pragma unroll
    for (int nt = 0; nt < 32; ++nt) {
        const int col = h * DH + nt * 8 + t4 * 2;
        *(__half2*)&Og[(size_t)tg * Q_SIZE + col] =
            __floats2half2_rn(o[nt][0] * i0, o[nt][1] * i0);
        *(__half2*)&Og[(size_t)(tg + 8) * Q_SIZE + col] =
            __floats2half2_rn(o[nt][2] * i1, o[nt][3] * i1);
    }
}

// ---------------------------------------------------------------------------
// Elementwise fp32 -> fp16 convert
// ---------------------------------------------------------------------------
__global__ __launch_bounds__(256)
void convert_h_kernel(const float* __restrict__ in, __half* __restrict__ out, int n)
{
    int i = (blockIdx.x * 256 + threadIdx.x) * 4;
    if (i < n) {
        float4 v = *(const float4*)&in[i];
        *(__half2*)&out[i]     = __floats2half2_rn(v.x, v.y);
        *(__half2*)&out[i + 2] = __floats2half2_rn(v.z, v.w);
    }
}

// ---------------------------------------------------------------------------
// Fast fp32->fp16 transpose, 64x64 tiles (weights)
// ---------------------------------------------------------------------------
__global__ __launch_bounds__(256)
void transpose_f2h(const float* __restrict__ in, __half* __restrict__ out, int R, int C)
{
    __shared__ float tile[64][65];
    const int c0 = blockIdx.x * 64, r0 = blockIdx.y * 64;
    const int tid = threadIdx.x;
    const int lx = tid & 15;
    const int ly = tid >> 4;
    #pragma unroll
    for (int i = 0; i < 4; i++) {
        const int r = ly + i * 16;
        float4 v = *(const float4*)&in[(size_t)(r0 + r) * C + c0 + lx * 4];
        tile[lx * 4 + 0][r] = v.x;
        tile[lx * 4 + 1][r] = v.y;
        tile[lx * 4 + 2][r] = v.z;
        tile[lx * 4 + 3][r] = v.w;
    }
    __syncthreads();
    const int wx = tid & 31;
    const int wy = tid >> 5;
    #pragma unroll
    for (int i = 0; i < 8; i++) {
        const int c = wy + i * 8;
        *(__half2*)&out[(size_t)(c0 + c) * R + r0 + wx * 2] =
            __floats2half2_rn(tile[c][wx * 2], tile[c][wx * 2 + 1]);
    }
}

// ---------------------------------------------------------------------------
// Fused RMSNorm + NeoX RoPE, warp-per-(t,h)
// ---------------------------------------------------------------------------
__global__ __launch_bounds__(128)
void normrope_kernel(const float* __restrict__ qkv,
                     const int*   __restrict__ positions,
                     const float* __restrict__ qw,
                     const float* __restrict__ kw,
                     __half* __restrict__ q_out,
                     __half* __restrict__ k_out,
                     __half* __restrict__ v_out)
{
    const int wg = blockIdx.x * 4 + (threadIdx.x >> 5);
    const int t = wg >> 4, h = wg & 15;
    const int lane = threadIdx.x & 31;
    const int pos = positions[t];
    const size_t row = (size_t)t * QKV_N;
    const size_t obase = (size_t)t * Q_SIZE + h * DH;

    float c[4], sn[4];
    #pragma unroll
    for (int i = 0; i < 4; i++) {
        const float fi = (float)(lane + 32 * i);
        const float fr = expf(-fi * (LN_THETA / 128.0f));
        sincosf((float)pos * fr, &sn[i], &c[i]);
    }

    #pragma unroll
    for (int sec = 0; sec < 3; sec++) {
        const size_t base = row + sec * Q_SIZE + h * DH;
        float x[8];
        #pragma unroll
        for (int i = 0; i < 8; i++) x[i] = qkv[base + lane + 32 * i];
        float ss = 0.0f;
        #pragma unroll
        for (int i = 0; i < 8; i++) ss += x[i] * x[i];
        #pragma unroll
        for (int off = 16; off > 0; off >>= 1) ss += __shfl_xor_sync(0xffffffffu, ss, off);
        const float rs = rsqrtf(ss * (1.0f / DH) + EPS);

        float v[8];
        #pragma unroll
        for (int i = 0; i < 8; i++) {
            float w = 1.0f;
            if (sec == 0) w = qw[lane + 32 * i];
            else if (sec == 1) w = kw[lane + 32 * i];
            v[i] = x[i] * rs * w;
        }
        if (sec < 2) {
            __half* outp = sec == 0 ? q_out : k_out;
            #pragma unroll
            for (int i = 0; i < 4; i++) {
                outp[obase + lane + 32 * i]       = __float2half(v[i] * c[i] - v[i + 4] * sn[i]);
                outp[obase + lane + 32 * i + 128] = __float2half(v[i + 4] * c[i] + v[i] * sn[i]);
            }
        } else {
            #pragma unroll
            for (int i = 0; i < 8; i++)
                v_out[obase + lane + 32 * i] = __float2half(v[i]);
        }
    }
}

// ---------------------------------------------------------------------------
// Launch
// ---------------------------------------------------------------------------
extern "C" void kernel_launch(void* const* d_in, const int* in_sizes, int n_in,
                              void* d_out, int out_size)
{
    const float* hidden    = (const float*)d_in[0];
    const int*   positions = (const int*)  d_in[1];
    const float* w_qkv     = (const float*)d_in[2];
    const float* w_o       = (const float*)d_in[3];
    const float* qw        = (const float*)d_in[4];
    const float* kw        = (const float*)d_in[5];
    float* out = (float*)d_out;

    __half *hid_h, *wqkv_h, *wo_h, *qh, *kh, *vh, *attn_h;
    float *qkv;
    cudaGetSymbolAddress((void**)&hid_h,  g_hidden_h);
    cudaGetSymbolAddress((void**)&wqkv_h, g_wqkv_h);
    cudaGetSymbolAddress((void**)&wo_h,   g_wo_h);
    cudaGetSymbolAddress((void**)&qkv,    g_qkv);
    cudaGetSymbolAddress((void**)&qh,     g_qh);
    cudaGetSymbolAddress((void**)&kh,     g_kh);
    cudaGetSymbolAddress((void**)&vh,     g_vh);
    cudaGetSymbolAddress((void**)&attn_h, g_attn_h);

    cudaFuncSetAttribute(h_gemm<false, false, false>, cudaFuncAttributeMaxDynamicSharedMemorySize, SMEM_BYTES);
    cudaFuncSetAttribute(flash_kernel, cudaFuncAttributeMaxDynamicSharedMemorySize, FLASH_SMEM);

    // 0) operand conversions / transposes (weights only)
    convert_h_kernel<<<(T_SEQ * HID / 4 + 255) / 256, 256>>>(hidden, hid_h, T_SEQ * HID);
    transpose_f2h<<<dim3(QKV_N / 64, HID / 64), 256>>>(w_qkv, wqkv_h, HID, QKV_N);
    transpose_f2h<<<dim3(HID / 64,   HID / 64), 256>>>(w_o,   wo_h,   HID, HID);

    // 1) qkv = hidden @ w_qkv  (fp32 out for exact rmsnorm)
    h_gemm<false, false, false><<<dim3(QKV_N / BN, T_SEQ / BM, 1), 256, SMEM_BYTES>>>(
        hid_h, wqkv_h, qkv, T_SEQ, QKV_N, HID, HID, HID, QKV_N, 0, 0, 0);

    // 2) rmsnorm + rope -> fp16 q/k/v
    normrope_kernel<<<T_SEQ * NH / 4, 128>>>(qkv, positions, qw, kw, qh, kh, vh);

    // 3) fused causal attention (full D per CTA, row-major V, 2 CTAs/SM)
    flash_kernel<<<dim3(T_SEQ / FQM, NH, 1), 128, FLASH_SMEM>>>(qh, kh, vh, attn_h);

    // 4) out = attn @ w_o (fp32 out)
    h_gemm<false, false, false><<<dim3(HID / BN, T_SEQ / BM, 1), 256, SMEM_BYTES>>>(
        attn_h, wo_h, out, T_SEQ, HID, Q_SIZE, Q_SIZE, Q_SIZE, HID, 0, 0, 0);

    (void)in_sizes; (void)n_in; (void)out_size;
}

// round 16
// speedup vs baseline: 1.0701x; 1.0701x over previous
#include <cuda_runtime.h>
#include <cuda_fp16.h>
#include <math.h>
#include <float.h>
#include <cstdint>

// Problem constants
#define T_SEQ 2048
#define HID   4096
#define NH    16
#define DH    256
#define QKV_N (3 * NH * DH)      // 12288
#define Q_SIZE (NH * DH)         // 4096
#define EPS   1e-6f
#define LN_THETA 9.210340371976184f   // ln(10000)

// GEMM tile config (fp16 engine): CTA 128x128, warp 32x64, 8 warps, BK=64
#define BM 128
#define BN 128
#define BK 64
#define STRIDE 72
#define STAGES 3
#define STAGE_BYTES ((BM + BN) * STRIDE * 2)   // 36864
#define SMEM_BYTES (STAGES * STAGE_BYTES)      // 110592

// Flash v6: q-tile 128, kv-tile 64, 8 warps, FULL D=256, K/V double-buffered,
// V row-major via ldmatrix.trans, paired q-tiles per CTA (balanced single wave).
#define FQM 128
#define FKV 64
#define QSTR 264                   // 256 + 8 pad (halfs)
#define FOFF_K0 (FQM * QSTR * 2)               // 67584
#define FK_BYTES (FKV * QSTR * 2)              // 33792
#define FOFF_V0 (FOFF_K0 + 2 * FK_BYTES)       // 135168
#define FV_BYTES (FKV * QSTR * 2)              // 33792
#define FLASH_SMEM (FOFF_V0 + 2 * FV_BYTES)    // 202752

// ---------------------------------------------------------------------------
// Scratch (static device globals)
// ---------------------------------------------------------------------------
__device__ __half g_hidden_h[(size_t)T_SEQ * HID];
__device__ __half g_wqkv_h[(size_t)QKV_N * HID];
__device__ __half g_wo_h[(size_t)HID * Q_SIZE];
__device__ float  g_qkv[(size_t)T_SEQ * QKV_N];
__device__ __half g_qh[(size_t)T_SEQ * NH * DH];
__device__ __half g_kh[(size_t)T_SEQ * NH * DH];
__device__ __half g_vh[(size_t)T_SEQ * NH * DH];
__device__ __half g_attn_h[(size_t)T_SEQ * NH * DH];

// ---------------------------------------------------------------------------
// PTX helpers
// ---------------------------------------------------------------------------
__device__ __forceinline__ uint32_t smem_u32(const void* p) {
    uint32_t a;
    asm("{ .reg .u64 t; cvta.to.shared.u64 t, %1; cvt.u32.u64 %0, t; }" : "=r"(a) : "l"(p));
    return a;
}
#define CP_ASYNC16(dst, src) \
    asm volatile("cp.async.cg.shared.global [%0], [%1], 16;" :: "r"(dst), "l"(src))
#define CP_COMMIT() asm volatile("cp.async.commit_group;" ::: "memory")
#define CP_WAIT(n)  asm volatile("cp.async.wait_group %0;" :: "n"(n) : "memory")

__device__ __forceinline__ void ldmx4(uint32_t* r, uint32_t addr) {
    asm volatile("ldmatrix.sync.aligned.m8n8.x4.shared.b16 {%0,%1,%2,%3}, [%4];"
        : "=r"(r[0]), "=r"(r[1]), "=r"(r[2]), "=r"(r[3]) : "r"(addr));
}
__device__ __forceinline__ void ldmx4_trans(uint32_t* r, uint32_t addr) {
    asm volatile("ldmatrix.sync.aligned.m8n8.x4.trans.shared.b16 {%0,%1,%2,%3}, [%4];"
        : "=r"(r[0]), "=r"(r[1]), "=r"(r[2]), "=r"(r[3]) : "r"(addr));
}
__device__ __forceinline__ void mma_f16(float* d, const uint32_t* a, const uint32_t* b) {
    asm volatile(
        "mma.sync.aligned.m16n8k16.row.col.f32.f16.f16.f32 "
        "{%0,%1,%2,%3}, {%4,%5,%6,%7}, {%8,%9}, {%0,%1,%2,%3};"
        : "+f"(d[0]), "+f"(d[1]), "+f"(d[2]), "+f"(d[3])
        : "r"(a[0]), "r"(a[1]), "r"(a[2]), "r"(a[3]), "r"(b[0]), "r"(b[1]));
}
__device__ __forceinline__ uint32_t h2pack(float a, float b) {
    __half2 h = __floats2half2_rn(a, b);
    return *(uint32_t*)&h;
}

// ---------------------------------------------------------------------------
// fp16 mma.sync GEMM (unchanged from R8)
// ---------------------------------------------------------------------------
template<bool CSKIP, bool CKLIM, bool HALF_OUT>
__global__ __launch_bounds__(256, 2)
void h_gemm(const __half* __restrict__ A, const __half* __restrict__ B, void* __restrict__ Cv,
            int M, int N, int K, int lda, int ldb, int ldc,
            long long bA, long long bB, long long bC)
{
    const int row0 = blockIdx.y * BM;
    const int col0 = blockIdx.x * BN;
    if (CSKIP && col0 >= row0 + BM) return;
    const int Keff = CKLIM ? min(K, row0 + BM) : K;
    const int nCh = Keff / BK;

    A += (long long)blockIdx.z * bA;
    B += (long long)blockIdx.z * bB;

    extern __shared__ char smem[];
    const uint32_t sbase = smem_u32(smem);

    const int tid = threadIdx.x;
    const int wid = tid >> 5, lane = tid & 31;
    const int g = lane >> 2, t4 = lane & 3;
    const int warpM = (wid & 3) * 32;
    const int warpN = (wid >> 2) * 64;
    const int lrow = lane & 7, lsel = lane >> 3;

    const uint32_t aoff = ((warpM + (lsel & 1) * 8 + lrow) * STRIDE + (lsel >> 1) * 8) * 2;
    const uint32_t boff = ((warpN + (lsel >> 1) * 8 + lrow) * STRIDE + (lsel & 1) * 8) * 2;

    float acc[2][8][4];
    #pragma unroll
    for (int i = 0; i < 2; i++)
        #pragma unroll
        for (int j = 0; j < 8; j++)
            #pragma unroll
            for (int q = 0; q < 4; q++) acc[i][j][q] = 0.0f;

    auto load_stage = [&](int st, int ch) {
        const uint32_t sA = sbase + st * STAGE_BYTES;
        const uint32_t sB = sA + BM * STRIDE * 2;
        const int k0 = ch * BK;
        #pragma unroll
        for (int i = 0; i < 4; i++) {
            int u = tid + i * 256;
            int r = u >> 3, cu = u & 7;
            CP_ASYNC16(sA + (r * STRIDE + cu * 8) * 2,
                       &A[(size_t)(row0 + r) * lda + k0 + cu * 8]);
        }
        #pragma unroll
        for (int i = 0; i < 4; i++) {
            int u = tid + i * 256;
            int r = u >> 3, cu = u & 7;
            CP_ASYNC16(sB + (r * STRIDE + cu * 8) * 2,
                       &B[(size_t)(col0 + r) * ldb + k0 + cu * 8]);
        }
    };

    auto compute_k16 = [&](uint32_t sA, uint32_t sB, int kk) {
        uint32_t a[2][4];
        ldmx4(a[0], sA + aoff + kk * 32);
        ldmx4(a[1], sA + aoff + 16 * STRIDE * 2 + kk * 32);
        uint32_t b[8][2];
        #pragma unroll
        for (int j = 0; j < 4; ++j) {
            uint32_t r[4];
            ldmx4(r, sB + boff + j * 16 * STRIDE * 2 + kk * 32);
            b[2 * j][0] = r[0]; b[2 * j][1] = r[1];
            b[2 * j + 1][0] = r[2]; b[2 * j + 1][1] = r[3];
        }
        #pragma unroll
        for (int nt = 0; nt < 8; ++nt) {
            mma_f16(acc[0][nt], a[0], b[nt]);
            mma_f16(acc[1][nt], a[1], b[nt]);
        }
    };

    #pragma unroll
    for (int p = 0; p < STAGES - 1; ++p) {
        if (p < nCh) load_stage(p, p);
        CP_COMMIT();
    }

    for (int c = 0; c < nCh; ++c) {
        CP_WAIT(STAGES - 2);
        __syncthreads();

        const uint32_t sA = sbase + (c % STAGES) * STAGE_BYTES;
        const uint32_t sB = sA + BM * STRIDE * 2;

        compute_k16(sA, sB, 0);
        if (c + STAGES - 1 < nCh) load_stage((c + STAGES - 1) % STAGES, c + STAGES - 1);
        CP_COMMIT();
        #pragma unroll
        for (int kk = 1; kk < 4; ++kk)
            compute_k16(sA, sB, kk);
    }

    #pragma unroll
    for (int mt = 0; mt < 2; mt++) {
        const int r0 = row0 + warpM + mt * 16 + g;
        #pragma unroll
        for (int nt = 0; nt < 8; nt++) {
            const int cc = col0 + warpN + nt * 8 + t4 * 2;
            if (HALF_OUT) {
                __half* C = (__half*)Cv + (long long)blockIdx.z * bC;
                *(__half2*)&C[(size_t)r0 * ldc + cc] =
                    __floats2half2_rn(acc[mt][nt][0], acc[mt][nt][1]);
                *(__half2*)&C[(size_t)(r0 + 8) * ldc + cc] =
                    __floats2half2_rn(acc[mt][nt][2], acc[mt][nt][3]);
            } else {
                float* C = (float*)Cv + (long long)blockIdx.z * bC;
                *(float2*)&C[(size_t)r0 * ldc + cc]       = make_float2(acc[mt][nt][0], acc[mt][nt][1]);
                *(float2*)&C[(size_t)(r0 + 8) * ldc + cc] = make_float2(acc[mt][nt][2], acc[mt][nt][3]);
            }
        }
    }
}

// ---------------------------------------------------------------------------
// Flash v6: q-tile 128, 8 warps, register-P, FULL D=256, V via ldmatrix.trans.
// Each CTA processes TWO q-tiles (15-bx then bx) => uniform 34 kv-units/CTA,
// 128 CTAs = one balanced wave. Warp w owns rows w*16..w*16+15 of each tile.
// ---------------------------------------------------------------------------
__global__ __launch_bounds__(256, 1)
void flash_kernel(const __half* __restrict__ Qg, const __half* __restrict__ Kg,
                  const __half* __restrict__ Vg, __half* __restrict__ Og)
{
    const int h = blockIdx.y;

    extern __shared__ char sm[];
    const uint32_t sb = smem_u32(sm);
    const uint32_t Qs = sb;

    const int tid = threadIdx.x;
    const int w = tid >> 5, lane = tid & 31;
    const int g = lane >> 2, t4 = lane & 3;
    const int lrow = lane & 7, lsel = lane >> 3;

    const __half* Qp = Qg + (size_t)h * DH;
    const __half* Kp = Kg + (size_t)h * DH;
    const __half* Vp = Vg + (size_t)h * DH;

    const uint32_t aoffQ = ((w * 16 + (lsel & 1) * 8 + lrow) * QSTR + (lsel >> 1) * 8) * 2;
    const uint32_t boffK = (((lsel >> 1) * 8 + lrow) * QSTR + (lsel & 1) * 8) * 2;
    const uint32_t boffV = (((lsel & 1) * 8 + lrow) * QSTR + (lsel >> 1) * 8) * 2;

    auto load_kv = [&](int buf, int kv0) {
        const uint32_t Ks = sb + FOFF_K0 + buf * FK_BYTES;
        const uint32_t Vs = sb + FOFF_V0 + buf * FV_BYTES;
        #pragma unroll
        for (int i = 0; i < 8; i++) {
            int u = tid + i * 256;
            int r = u >> 5, cu = u & 31;
            CP_ASYNC16(Ks + (r * QSTR + cu * 8) * 2, Kp + (size_t)(kv0 + r) * Q_SIZE + cu * 8);
        }
        #pragma unroll
        for (int i = 0; i < 8; i++) {
            int u = tid + i * 256;
            int r = u >> 5, cu = u & 31;
            CP_ASYNC16(Vs + (r * QSTR + cu * 8) * 2, Vp + (size_t)(kv0 + r) * Q_SIZE + cu * 8);
        }
    };

    for (int pass = 0; pass < 2; ++pass) {
        const int qtile = pass == 0 ? (15 - blockIdx.x) : blockIdx.x;  // big tile first
        const int q0 = qtile * FQM;

        __syncthreads();            // smem from previous pass fully consumed

        // Q tile (128 x 256): 4096 16B-units, 16 per thread
        #pragma unroll
        for (int i = 0; i < 16; i++) {
            int u = tid + i * 256;
            int r = u >> 5, cu = u & 31;
            CP_ASYNC16(Qs + (r * QSTR + cu * 8) * 2, Qp + (size_t)(q0 + r) * Q_SIZE + cu * 8);
        }

        float m0 = -1e30f, m1 = -1e30f, l0 = 0.0f, l1 = 0.0f;
        float o[32][4];
        #pragma unroll
        for (int i = 0; i < 32; i++)
            #pragma unroll
            for (int q = 0; q < 4; q++) o[i][q] = 0.0f;

        const int nkv = 2 * qtile + 2;
        load_kv(0, 0);              // prologue: Q + KV(0) in one group
        CP_COMMIT();

        for (int it = 0; it < nkv; ++it) {
            const int kv0 = it * FKV;
            CP_WAIT(0);
            __syncthreads();
            if (it + 1 < nkv) load_kv((it + 1) & 1, kv0 + FKV);
            CP_COMMIT();

            const uint32_t Ks = sb + FOFF_K0 + (it & 1) * FK_BYTES;
            const uint32_t Vs = sb + FOFF_V0 + (it & 1) * FV_BYTES;

            if (kv0 > q0 + w * 16 + 15) continue;   // warp fully masked

            // S = Q K^T
            float s[8][4];
            #pragma unroll
            for (int i = 0; i < 8; i++)
                #pragma unroll
                for (int q = 0; q < 4; q++) s[i][q] = 0.0f;
            #pragma unroll
            for (int ks = 0; ks < 16; ++ks) {
                uint32_t a[4];
                ldmx4(a, Qs + aoffQ + ks * 32);
                #pragma unroll
                for (int j = 0; j < 4; ++j) {
                    uint32_t r4[4];
                    ldmx4(r4, Ks + boffK + j * 16 * QSTR * 2 + ks * 32);
                    mma_f16(s[2 * j], a, r4);
                    mma_f16(s[2 * j + 1], a, r4 + 2);
                }
            }

            // causal mask on diagonal-crossing tiles
            if (kv0 + FKV - 1 > q0 + w * 16) {
                const int rowg = q0 + w * 16 + g;
                #pragma unroll
                for (int nt = 0; nt < 8; ++nt) {
                    const int col = kv0 + nt * 8 + t4 * 2;
                    if (col     > rowg)     s[nt][0] = -1e30f;
                    if (col + 1 > rowg)     s[nt][1] = -1e30f;
                    if (col     > rowg + 8) s[nt][2] = -1e30f;
                    if (col + 1 > rowg + 8) s[nt][3] = -1e30f;
                }
            }

            // online softmax, both rows interleaved (independent shuffle chains)
            float mx0 = -1e30f, mx1 = -1e30f;
            #pragma unroll
            for (int nt = 0; nt < 8; ++nt) {
                mx0 = fmaxf(mx0, fmaxf(s[nt][0], s[nt][1]));
                mx1 = fmaxf(mx1, fmaxf(s[nt][2], s[nt][3]));
            }
            mx0 = fmaxf(mx0, __shfl_xor_sync(0xffffffffu, mx0, 1));
            mx1 = fmaxf(mx1, __shfl_xor_sync(0xffffffffu, mx1, 1));
            mx0 = fmaxf(mx0, __shfl_xor_sync(0xffffffffu, mx0, 2));
            mx1 = fmaxf(mx1, __shfl_xor_sync(0xffffffffu, mx1, 2));
            const float mn0 = fmaxf(m0, mx0);
            const float mn1 = fmaxf(m1, mx1);
            float sum0 = 0.0f, sum1 = 0.0f;
            #pragma unroll
            for (int nt = 0; nt < 8; ++nt) {
                float p0 = __expf(s[nt][0] - mn0);
                float p1 = __expf(s[nt][1] - mn0);
                float p2 = __expf(s[nt][2] - mn1);
                float p3 = __expf(s[nt][3] - mn1);
                s[nt][0] = p0; s[nt][1] = p1; s[nt][2] = p2; s[nt][3] = p3;
                sum0 += p0 + p1;
                sum1 += p2 + p3;
            }
            sum0 += __shfl_xor_sync(0xffffffffu, sum0, 1);
            sum1 += __shfl_xor_sync(0xffffffffu, sum1, 1);
            sum0 += __shfl_xor_sync(0xffffffffu, sum0, 2);
            sum1 += __shfl_xor_sync(0xffffffffu, sum1, 2);
            if (mn0 > m0) {
                const float sc = __expf(m0 - mn0);
                l0 = l0 * sc + sum0; m0 = mn0;
                #pragma unroll
                for (int nt = 0; nt < 32; ++nt) { o[nt][0] *= sc; o[nt][1] *= sc; }
            } else l0 += sum0;
            if (mn1 > m1) {
                const float sc = __expf(m1 - mn1);
                l1 = l1 * sc + sum1; m1 = mn1;
                #pragma unroll
                for (int nt = 0; nt < 32; ++nt) { o[nt][2] *= sc; o[nt][3] *= sc; }
            } else l1 += sum1;

            // O += P V  (P from S registers; V^T frags via ldmatrix.trans)
            #pragma unroll
            for (int ks2 = 0; ks2 < 4; ++ks2) {
                uint32_t a[4];
                a[0] = h2pack(s[2 * ks2][0],     s[2 * ks2][1]);
                a[1] = h2pack(s[2 * ks2][2],     s[2 * ks2][3]);
                a[2] = h2pack(s[2 * ks2 + 1][0], s[2 * ks2 + 1][1]);
                a[3] = h2pack(s[2 * ks2 + 1][2], s[2 * ks2 + 1][3]);
                const uint32_t vrow = Vs + boffV + ks2 * 16 * QSTR * 2;
                #pragma unroll
                for (int j = 0; j < 16; ++j) {
                    uint32_t r4[4];
                    ldmx4_trans(r4, vrow + j * 32);
                    mma_f16(o[2 * j], a, r4);
                    mma_f16(o[2 * j + 1], a, r4 + 2);
                }
            }
        }

        // write O / l for this q-tile
        const float i0 = 1.0f / l0, i1 = 1.0f / l1;
        const int tg = q0 + w * 16 + g;
        #pragma unroll
        for (int nt = 0; nt < 32; ++nt) {
            const int col = h * DH + nt * 8 + t4 * 2;
            *(__half2*)&Og[(size_t)tg * Q_SIZE + col] =
                __floats2half2_rn(o[nt][0] * i0, o[nt][1] * i0);
            *(__half2*)&Og[(size_t)(tg + 8) * Q_SIZE + col] =
                __floats2half2_rn(o[nt][2] * i1, o[nt][3] * i1);
        }
    }
}

// ---------------------------------------------------------------------------
// Elementwise fp32 -> fp16 convert
// ---------------------------------------------------------------------------
__global__ __launch_bounds__(256)
void convert_h_kernel(const float* __restrict__ in, __half* __restrict__ out, int n)
{
    int i = (blockIdx.x * 256 + threadIdx.x) * 4;
    if (i < n) {
        float4 v = *(const float4*)&in[i];
        *(__half2*)&out[i]     = __floats2half2_rn(v.x, v.y);
        *(__half2*)&out[i + 2] = __floats2half2_rn(v.z, v.w);
    }
}

// ---------------------------------------------------------------------------
// Fast fp32->fp16 transpose, 64x64 tiles (weights)
// ---------------------------------------------------------------------------
__global__ __launch_bounds__(256)
void transpose_f2h(const float* __restrict__ in, __half* __restrict__ out, int R, int C)
{
    __shared__ float tile[64][65];
    const int c0 = blockIdx.x * 64, r0 = blockIdx.y * 64;
    const int tid = threadIdx.x;
    const int lx = tid & 15;
    const int ly = tid >> 4;
    #pragma unroll
    for (int i = 0; i < 4; i++) {
        const int r = ly + i * 16;
        float4 v = *(const float4*)&in[(size_t)(r0 + r) * C + c0 + lx * 4];
        tile[lx * 4 + 0][r] = v.x;
        tile[lx * 4 + 1][r] = v.y;
        tile[lx * 4 + 2][r] = v.z;
        tile[lx * 4 + 3][r] = v.w;
    }
    __syncthreads();
    const int wx = tid & 31;
    const int wy = tid >> 5;
    #pragma unroll
    for (int i = 0; i < 8; i++) {
        const int c = wy + i * 8;
        *(__half2*)&out[(size_t)(c0 + c) * R + r0 + wx * 2] =
            __floats2half2_rn(tile[c][wx * 2], tile[c][wx * 2 + 1]);
    }
}

// ---------------------------------------------------------------------------
// Fused RMSNorm + NeoX RoPE, warp-per-(t,h)
// ---------------------------------------------------------------------------
__global__ __launch_bounds__(128)
void normrope_kernel(const float* __restrict__ qkv,
                     const int*   __restrict__ positions,
                     const float* __restrict__ qw,
                     const float* __restrict__ kw,
                     __half* __restrict__ q_out,
                     __half* __restrict__ k_out,
                     __half* __restrict__ v_out)
{
    const int wg = blockIdx.x * 4 + (threadIdx.x >> 5);
    const int t = wg >> 4, h = wg & 15;
    const int lane = threadIdx.x & 31;
    const int pos = positions[t];
    const size_t row = (size_t)t * QKV_N;
    const size_t obase = (size_t)t * Q_SIZE + h * DH;

    float c[4], sn[4];
    #pragma unroll
    for (int i = 0; i < 4; i++) {
        const float fi = (float)(lane + 32 * i);
        const float fr = expf(-fi * (LN_THETA / 128.0f));
        sincosf((float)pos * fr, &sn[i], &c[i]);
    }

    #pragma unroll
    for (int sec = 0; sec < 3; sec++) {
        const size_t base = row + sec * Q_SIZE + h * DH;
        float x[8];
        #pragma unroll
        for (int i = 0; i < 8; i++) x[i] = qkv[base + lane + 32 * i];
        float ss = 0.0f;
        #pragma unroll
        for (int i = 0; i < 8; i++) ss += x[i] * x[i];
        #pragma unroll
        for (int off = 16; off > 0; off >>= 1) ss += __shfl_xor_sync(0xffffffffu, ss, off);
        const float rs = rsqrtf(ss * (1.0f / DH) + EPS);

        float v[8];
        #pragma unroll
        for (int i = 0; i < 8; i++) {
            float w = 1.0f;
            if (sec == 0) w = qw[lane + 32 * i];
            else if (sec == 1) w = kw[lane + 32 * i];
            v[i] = x[i] * rs * w;
        }
        if (sec < 2) {
            __half* outp = sec == 0 ? q_out : k_out;
            #pragma unroll
            for (int i = 0; i < 4; i++) {
                outp[obase + lane + 32 * i]       = __float2half(v[i] * c[i] - v[i + 4] * sn[i]);
                outp[obase + lane + 32 * i + 128] = __float2half(v[i + 4] * c[i] + v[i] * sn[i]);
            }
        } else {
            #pragma unroll
            for (int i = 0; i < 8; i++)
                v_out[obase + lane + 32 * i] = __float2half(v[i]);
        }
    }
}

// ---------------------------------------------------------------------------
// Launch
// ---------------------------------------------------------------------------
extern "C" void kernel_launch(void* const* d_in, const int* in_sizes, int n_in,
                              void* d_out, int out_size)
{
    const float* hidden    = (const float*)d_in[0];
    const int*   positions = (const int*)  d_in[1];
    const float* w_qkv     = (const float*)d_in[2];
    const float* w_o       = (const float*)d_in[3];
    const float* qw        = (const float*)d_in[4];
    const float* kw        = (const float*)d_in[5];
    float* out = (float*)d_out;

    __half *hid_h, *wqkv_h, *wo_h, *qh, *kh, *vh, *attn_h;
    float *qkv;
    cudaGetSymbolAddress((void**)&hid_h,  g_hidden_h);
    cudaGetSymbolAddress((void**)&wqkv_h, g_wqkv_h);
    cudaGetSymbolAddress((void**)&wo_h,   g_wo_h);
    cudaGetSymbolAddress((void**)&qkv,    g_qkv);
    cudaGetSymbolAddress((void**)&qh,     g_qh);
    cudaGetSymbolAddress((void**)&kh,     g_kh);
    cudaGetSymbolAddress((void**)&vh,     g_vh);
    cudaGetSymbolAddress((void**)&attn_h, g_attn_h);

    cudaFuncSetAttribute(h_gemm<false, false, false>, cudaFuncAttributeMaxDynamicSharedMemorySize, SMEM_BYTES);
    cudaFuncSetAttribute(flash_kernel, cudaFuncAttributeMaxDynamicSharedMemorySize, FLASH_SMEM);

    // 0) operand conversions / transposes (weights only)
    convert_h_kernel<<<(T_SEQ * HID / 4 + 255) / 256, 256>>>(hidden, hid_h, T_SEQ * HID);
    transpose_f2h<<<dim3(QKV_N / 64, HID / 64), 256>>>(w_qkv, wqkv_h, HID, QKV_N);
    transpose_f2h<<<dim3(HID / 64,   HID / 64), 256>>>(w_o,   wo_h,   HID, HID);

    // 1) qkv = hidden @ w_qkv  (fp32 out for exact rmsnorm)
    h_gemm<false, false, false><<<dim3(QKV_N / BN, T_SEQ / BM, 1), 256, SMEM_BYTES>>>(
        hid_h, wqkv_h, qkv, T_SEQ, QKV_N, HID, HID, HID, QKV_N, 0, 0, 0);

    // 2) rmsnorm + rope -> fp16 q/k/v
    normrope_kernel<<<T_SEQ * NH / 4, 128>>>(qkv, positions, qw, kw, qh, kh, vh);

    // 3) fused causal attention: paired q-tiles, balanced single wave
    flash_kernel<<<dim3(T_SEQ / FQM / 2, NH, 1), 256, FLASH_SMEM>>>(qh, kh, vh, attn_h);

    // 4) out = attn @ w_o (fp32 out)
    h_gemm<false, false, false><<<dim3(HID / BN, T_SEQ / BM, 1), 256, SMEM_BYTES>>>(
        attn_h, wo_h, out, T_SEQ, HID, Q_SIZE, Q_SIZE, Q_SIZE, HID, 0, 0, 0);

    (void)in_sizes; (void)n_in; (void)out_size;
}

// round 17
// speedup vs baseline: 1.0761x; 1.0056x over previous
#include <cuda_runtime.h>
#include <cuda_fp16.h>
#include <math.h>
#include <float.h>
#include <cstdint>

// Problem constants
#define T_SEQ 2048
#define HID   4096
#define NH    16
#define DH    256
#define QKV_N (3 * NH * DH)      // 12288
#define Q_SIZE (NH * DH)         // 4096
#define EPS   1e-6f
#define LN_THETA 9.210340371976184f   // ln(10000)

// GEMM tile config (fp16 engine): CTA 128x128, warp 32x64, 8 warps, BK=64
#define BM 128
#define BN 128
#define BK 64
#define STRIDE 72
#define STAGES 3
#define STAGE_BYTES ((BM + BN) * STRIDE * 2)   // 36864
#define SMEM_BYTES (STAGES * STAGE_BYTES)      // 110592

// Flash v6: q-tile 128, kv-tile 64, 8 warps, FULL D=256, K/V double-buffered,
// V row-major via ldmatrix.trans, paired q-tiles per CTA (balanced single wave).
#define FQM 128
#define FKV 64
#define QSTR 264                   // 256 + 8 pad (halfs)
#define FOFF_K0 (FQM * QSTR * 2)               // 67584
#define FK_BYTES (FKV * QSTR * 2)              // 33792
#define FOFF_V0 (FOFF_K0 + 2 * FK_BYTES)       // 135168
#define FV_BYTES (FKV * QSTR * 2)              // 33792
#define FLASH_SMEM (FOFF_V0 + 2 * FV_BYTES)    // 202752

// ---------------------------------------------------------------------------
// Scratch (static device globals)
// ---------------------------------------------------------------------------
__device__ __half g_hidden_h[(size_t)T_SEQ * HID];
__device__ __half g_wqkv_h[(size_t)QKV_N * HID];
__device__ __half g_wo_h[(size_t)HID * Q_SIZE];
__device__ __half g_qkv_h[(size_t)T_SEQ * QKV_N];   // fp16 now (48 MB)
__device__ __half g_qh[(size_t)T_SEQ * NH * DH];
__device__ __half g_kh[(size_t)T_SEQ * NH * DH];
__device__ __half g_vh[(size_t)T_SEQ * NH * DH];
__device__ __half g_attn_h[(size_t)T_SEQ * NH * DH];

// ---------------------------------------------------------------------------
// PTX helpers
// ---------------------------------------------------------------------------
__device__ __forceinline__ uint32_t smem_u32(const void* p) {
    uint32_t a;
    asm("{ .reg .u64 t; cvta.to.shared.u64 t, %1; cvt.u32.u64 %0, t; }" : "=r"(a) : "l"(p));
    return a;
}
#define CP_ASYNC16(dst, src) \
    asm volatile("cp.async.cg.shared.global [%0], [%1], 16;" :: "r"(dst), "l"(src))
#define CP_COMMIT() asm volatile("cp.async.commit_group;" ::: "memory")
#define CP_WAIT(n)  asm volatile("cp.async.wait_group %0;" :: "n"(n) : "memory")

__device__ __forceinline__ void ldmx4(uint32_t* r, uint32_t addr) {
    asm volatile("ldmatrix.sync.aligned.m8n8.x4.shared.b16 {%0,%1,%2,%3}, [%4];"
        : "=r"(r[0]), "=r"(r[1]), "=r"(r[2]), "=r"(r[3]) : "r"(addr));
}
__device__ __forceinline__ void ldmx4_trans(uint32_t* r, uint32_t addr) {
    asm volatile("ldmatrix.sync.aligned.m8n8.x4.trans.shared.b16 {%0,%1,%2,%3}, [%4];"
        : "=r"(r[0]), "=r"(r[1]), "=r"(r[2]), "=r"(r[3]) : "r"(addr));
}
__device__ __forceinline__ void mma_f16(float* d, const uint32_t* a, const uint32_t* b) {
    asm volatile(
        "mma.sync.aligned.m16n8k16.row.col.f32.f16.f16.f32 "
        "{%0,%1,%2,%3}, {%4,%5,%6,%7}, {%8,%9}, {%0,%1,%2,%3};"
        : "+f"(d[0]), "+f"(d[1]), "+f"(d[2]), "+f"(d[3])
        : "r"(a[0]), "r"(a[1]), "r"(a[2]), "r"(a[3]), "r"(b[0]), "r"(b[1]));
}
__device__ __forceinline__ uint32_t h2pack(float a, float b) {
    __half2 h = __floats2half2_rn(a, b);
    return *(uint32_t*)&h;
}

// ---------------------------------------------------------------------------
// fp16 mma.sync GEMM (unchanged structure)
// ---------------------------------------------------------------------------
template<bool CSKIP, bool CKLIM, bool HALF_OUT>
__global__ __launch_bounds__(256, 2)
void h_gemm(const __half* __restrict__ A, const __half* __restrict__ B, void* __restrict__ Cv,
            int M, int N, int K, int lda, int ldb, int ldc,
            long long bA, long long bB, long long bC)
{
    const int row0 = blockIdx.y * BM;
    const int col0 = blockIdx.x * BN;
    if (CSKIP && col0 >= row0 + BM) return;
    const int Keff = CKLIM ? min(K, row0 + BM) : K;
    const int nCh = Keff / BK;

    A += (long long)blockIdx.z * bA;
    B += (long long)blockIdx.z * bB;

    extern __shared__ char smem[];
    const uint32_t sbase = smem_u32(smem);

    const int tid = threadIdx.x;
    const int wid = tid >> 5, lane = tid & 31;
    const int g = lane >> 2, t4 = lane & 3;
    const int warpM = (wid & 3) * 32;
    const int warpN = (wid >> 2) * 64;
    const int lrow = lane & 7, lsel = lane >> 3;

    const uint32_t aoff = ((warpM + (lsel & 1) * 8 + lrow) * STRIDE + (lsel >> 1) * 8) * 2;
    const uint32_t boff = ((warpN + (lsel >> 1) * 8 + lrow) * STRIDE + (lsel & 1) * 8) * 2;

    float acc[2][8][4];
    #pragma unroll
    for (int i = 0; i < 2; i++)
        #pragma unroll
        for (int j = 0; j < 8; j++)
            #pragma unroll
            for (int q = 0; q < 4; q++) acc[i][j][q] = 0.0f;

    auto load_stage = [&](int st, int ch) {
        const uint32_t sA = sbase + st * STAGE_BYTES;
        const uint32_t sB = sA + BM * STRIDE * 2;
        const int k0 = ch * BK;
        #pragma unroll
        for (int i = 0; i < 4; i++) {
            int u = tid + i * 256;
            int r = u >> 3, cu = u & 7;
            CP_ASYNC16(sA + (r * STRIDE + cu * 8) * 2,
                       &A[(size_t)(row0 + r) * lda + k0 + cu * 8]);
        }
        #pragma unroll
        for (int i = 0; i < 4; i++) {
            int u = tid + i * 256;
            int r = u >> 3, cu = u & 7;
            CP_ASYNC16(sB + (r * STRIDE + cu * 8) * 2,
                       &B[(size_t)(col0 + r) * ldb + k0 + cu * 8]);
        }
    };

    auto compute_k16 = [&](uint32_t sA, uint32_t sB, int kk) {
        uint32_t a[2][4];
        ldmx4(a[0], sA + aoff + kk * 32);
        ldmx4(a[1], sA + aoff + 16 * STRIDE * 2 + kk * 32);
        uint32_t b[8][2];
        #pragma unroll
        for (int j = 0; j < 4; ++j) {
            uint32_t r[4];
            ldmx4(r, sB + boff + j * 16 * STRIDE * 2 + kk * 32);
            b[2 * j][0] = r[0]; b[2 * j][1] = r[1];
            b[2 * j + 1][0] = r[2]; b[2 * j + 1][1] = r[3];
        }
        #pragma unroll
        for (int nt = 0; nt < 8; ++nt) {
            mma_f16(acc[0][nt], a[0], b[nt]);
            mma_f16(acc[1][nt], a[1], b[nt]);
        }
    };

    #pragma unroll
    for (int p = 0; p < STAGES - 1; ++p) {
        if (p < nCh) load_stage(p, p);
        CP_COMMIT();
    }

    for (int c = 0; c < nCh; ++c) {
        CP_WAIT(STAGES - 2);
        __syncthreads();

        const uint32_t sA = sbase + (c % STAGES) * STAGE_BYTES;
        const uint32_t sB = sA + BM * STRIDE * 2;

        compute_k16(sA, sB, 0);
        if (c + STAGES - 1 < nCh) load_stage((c + STAGES - 1) % STAGES, c + STAGES - 1);
        CP_COMMIT();
        #pragma unroll
        for (int kk = 1; kk < 4; ++kk)
            compute_k16(sA, sB, kk);
    }

    #pragma unroll
    for (int mt = 0; mt < 2; mt++) {
        const int r0 = row0 + warpM + mt * 16 + g;
        #pragma unroll
        for (int nt = 0; nt < 8; nt++) {
            const int cc = col0 + warpN + nt * 8 + t4 * 2;
            if (HALF_OUT) {
                __half* C = (__half*)Cv + (long long)blockIdx.z * bC;
                *(__half2*)&C[(size_t)r0 * ldc + cc] =
                    __floats2half2_rn(acc[mt][nt][0], acc[mt][nt][1]);
                *(__half2*)&C[(size_t)(r0 + 8) * ldc + cc] =
                    __floats2half2_rn(acc[mt][nt][2], acc[mt][nt][3]);
            } else {
                float* C = (float*)Cv + (long long)blockIdx.z * bC;
                *(float2*)&C[(size_t)r0 * ldc + cc]       = make_float2(acc[mt][nt][0], acc[mt][nt][1]);
                *(float2*)&C[(size_t)(r0 + 8) * ldc + cc] = make_float2(acc[mt][nt][2], acc[mt][nt][3]);
            }
        }
    }
}

// ---------------------------------------------------------------------------
// Flash v6 (unchanged from R16 winner): paired q-tiles, register-P, trans-V.
// ---------------------------------------------------------------------------
__global__ __launch_bounds__(256, 1)
void flash_kernel(const __half* __restrict__ Qg, const __half* __restrict__ Kg,
                  const __half* __restrict__ Vg, __half* __restrict__ Og)
{
    const int h = blockIdx.y;

    extern __shared__ char sm[];
    const uint32_t sb = smem_u32(sm);
    const uint32_t Qs = sb;

    const int tid = threadIdx.x;
    const int w = tid >> 5, lane = tid & 31;
    const int g = lane >> 2, t4 = lane & 3;
    const int lrow = lane & 7, lsel = lane >> 3;

    const __half* Qp = Qg + (size_t)h * DH;
    const __half* Kp = Kg + (size_t)h * DH;
    const __half* Vp = Vg + (size_t)h * DH;

    const uint32_t aoffQ = ((w * 16 + (lsel & 1) * 8 + lrow) * QSTR + (lsel >> 1) * 8) * 2;
    const uint32_t boffK = (((lsel >> 1) * 8 + lrow) * QSTR + (lsel & 1) * 8) * 2;
    const uint32_t boffV = (((lsel & 1) * 8 + lrow) * QSTR + (lsel >> 1) * 8) * 2;

    auto load_kv = [&](int buf, int kv0) {
        const uint32_t Ks = sb + FOFF_K0 + buf * FK_BYTES;
        const uint32_t Vs = sb + FOFF_V0 + buf * FV_BYTES;
        #pragma unroll
        for (int i = 0; i < 8; i++) {
            int u = tid + i * 256;
            int r = u >> 5, cu = u & 31;
            CP_ASYNC16(Ks + (r * QSTR + cu * 8) * 2, Kp + (size_t)(kv0 + r) * Q_SIZE + cu * 8);
        }
        #pragma unroll
        for (int i = 0; i < 8; i++) {
            int u = tid + i * 256;
            int r = u >> 5, cu = u & 31;
            CP_ASYNC16(Vs + (r * QSTR + cu * 8) * 2, Vp + (size_t)(kv0 + r) * Q_SIZE + cu * 8);
        }
    };

    for (int pass = 0; pass < 2; ++pass) {
        const int qtile = pass == 0 ? (15 - blockIdx.x) : blockIdx.x;  // big tile first
        const int q0 = qtile * FQM;

        __syncthreads();            // smem from previous pass fully consumed

        #pragma unroll
        for (int i = 0; i < 16; i++) {
            int u = tid + i * 256;
            int r = u >> 5, cu = u & 31;
            CP_ASYNC16(Qs + (r * QSTR + cu * 8) * 2, Qp + (size_t)(q0 + r) * Q_SIZE + cu * 8);
        }

        float m0 = -1e30f, m1 = -1e30f, l0 = 0.0f, l1 = 0.0f;
        float o[32][4];
        #pragma unroll
        for (int i = 0; i < 32; i++)
            #pragma unroll
            for (int q = 0; q < 4; q++) o[i][q] = 0.0f;

        const int nkv = 2 * qtile + 2;
        load_kv(0, 0);
        CP_COMMIT();

        for (int it = 0; it < nkv; ++it) {
            const int kv0 = it * FKV;
            CP_WAIT(0);
            __syncthreads();
            if (it + 1 < nkv) load_kv((it + 1) & 1, kv0 + FKV);
            CP_COMMIT();

            const uint32_t Ks = sb + FOFF_K0 + (it & 1) * FK_BYTES;
            const uint32_t Vs = sb + FOFF_V0 + (it & 1) * FV_BYTES;

            if (kv0 > q0 + w * 16 + 15) continue;

            float s[8][4];
            #pragma unroll
            for (int i = 0; i < 8; i++)
                #pragma unroll
                for (int q = 0; q < 4; q++) s[i][q] = 0.0f;
            #pragma unroll
            for (int ks = 0; ks < 16; ++ks) {
                uint32_t a[4];
                ldmx4(a, Qs + aoffQ + ks * 32);
                #pragma unroll
                for (int j = 0; j < 4; ++j) {
                    uint32_t r4[4];
                    ldmx4(r4, Ks + boffK + j * 16 * QSTR * 2 + ks * 32);
                    mma_f16(s[2 * j], a, r4);
                    mma_f16(s[2 * j + 1], a, r4 + 2);
                }
            }

            if (kv0 + FKV - 1 > q0 + w * 16) {
                const int rowg = q0 + w * 16 + g;
                #pragma unroll
                for (int nt = 0; nt < 8; ++nt) {
                    const int col = kv0 + nt * 8 + t4 * 2;
                    if (col     > rowg)     s[nt][0] = -1e30f;
                    if (col + 1 > rowg)     s[nt][1] = -1e30f;
                    if (col     > rowg + 8) s[nt][2] = -1e30f;
                    if (col + 1 > rowg + 8) s[nt][3] = -1e30f;
                }
            }

            float mx0 = -1e30f, mx1 = -1e30f;
            #pragma unroll
            for (int nt = 0; nt < 8; ++nt) {
                mx0 = fmaxf(mx0, fmaxf(s[nt][0], s[nt][1]));
                mx1 = fmaxf(mx1, fmaxf(s[nt][2], s[nt][3]));
            }
            mx0 = fmaxf(mx0, __shfl_xor_sync(0xffffffffu, mx0, 1));
            mx1 = fmaxf(mx1, __shfl_xor_sync(0xffffffffu, mx1, 1));
            mx0 = fmaxf(mx0, __shfl_xor_sync(0xffffffffu, mx0, 2));
            mx1 = fmaxf(mx1, __shfl_xor_sync(0xffffffffu, mx1, 2));
            const float mn0 = fmaxf(m0, mx0);
            const float mn1 = fmaxf(m1, mx1);
            float sum0 = 0.0f, sum1 = 0.0f;
            #pragma unroll
            for (int nt = 0; nt < 8; ++nt) {
                float p0 = __expf(s[nt][0] - mn0);
                float p1 = __expf(s[nt][1] - mn0);
                float p2 = __expf(s[nt][2] - mn1);
                float p3 = __expf(s[nt][3] - mn1);
                s[nt][0] = p0; s[nt][1] = p1; s[nt][2] = p2; s[nt][3] = p3;
                sum0 += p0 + p1;
                sum1 += p2 + p3;
            }
            sum0 += __shfl_xor_sync(0xffffffffu, sum0, 1);
            sum1 += __shfl_xor_sync(0xffffffffu, sum1, 1);
            sum0 += __shfl_xor_sync(0xffffffffu, sum0, 2);
            sum1 += __shfl_xor_sync(0xffffffffu, sum1, 2);
            if (mn0 > m0) {
                const float sc = __expf(m0 - mn0);
                l0 = l0 * sc + sum0; m0 = mn0;
                #pragma unroll
                for (int nt = 0; nt < 32; ++nt) { o[nt][0] *= sc; o[nt][1] *= sc; }
            } else l0 += sum0;
            if (mn1 > m1) {
                const float sc = __expf(m1 - mn1);
                l1 = l1 * sc + sum1; m1 = mn1;
                #pragma unroll
                for (int nt = 0; nt < 32; ++nt) { o[nt][2] *= sc; o[nt][3] *= sc; }
            } else l1 += sum1;

            #pragma unroll
            for (int ks2 = 0; ks2 < 4; ++ks2) {
                uint32_t a[4];
                a[0] = h2pack(s[2 * ks2][0],     s[2 * ks2][1]);
                a[1] = h2pack(s[2 * ks2][2],     s[2 * ks2][3]);
                a[2] = h2pack(s[2 * ks2 + 1][0], s[2 * ks2 + 1][1]);
                a[3] = h2pack(s[2 * ks2 + 1][2], s[2 * ks2 + 1][3]);
                const uint32_t vrow = Vs + boffV + ks2 * 16 * QSTR * 2;
                #pragma unroll
                for (int j = 0; j < 16; ++j) {
                    uint32_t r4[4];
                    ldmx4_trans(r4, vrow + j * 32);
                    mma_f16(o[2 * j], a, r4);
                    mma_f16(o[2 * j + 1], a, r4 + 2);
                }
            }
        }

        const float i0 = 1.0f / l0, i1 = 1.0f / l1;
        const int tg = q0 + w * 16 + g;
        #pragma unroll
        for (int nt = 0; nt < 32; ++nt) {
            const int col = h * DH + nt * 8 + t4 * 2;
            *(__half2*)&Og[(size_t)tg * Q_SIZE + col] =
                __floats2half2_rn(o[nt][0] * i0, o[nt][1] * i0);
            *(__half2*)&Og[(size_t)(tg + 8) * Q_SIZE + col] =
                __floats2half2_rn(o[nt][2] * i1, o[nt][3] * i1);
        }
    }
}

// ---------------------------------------------------------------------------
// Elementwise fp32 -> fp16 convert
// ---------------------------------------------------------------------------
__global__ __launch_bounds__(256)
void convert_h_kernel(const float* __restrict__ in, __half* __restrict__ out, int n)
{
    int i = (blockIdx.x * 256 + threadIdx.x) * 4;
    if (i < n) {
        float4 v = *(const float4*)&in[i];
        *(__half2*)&out[i]     = __floats2half2_rn(v.x, v.y);
        *(__half2*)&out[i + 2] = __floats2half2_rn(v.z, v.w);
    }
}

// ---------------------------------------------------------------------------
// Fast fp32->fp16 transpose, 64x64 tiles (weights)
// ---------------------------------------------------------------------------
__global__ __launch_bounds__(256)
void transpose_f2h(const float* __restrict__ in, __half* __restrict__ out, int R, int C)
{
    __shared__ float tile[64][65];
    const int c0 = blockIdx.x * 64, r0 = blockIdx.y * 64;
    const int tid = threadIdx.x;
    const int lx = tid & 15;
    const int ly = tid >> 4;
    #pragma unroll
    for (int i = 0; i < 4; i++) {
        const int r = ly + i * 16;
        float4 v = *(const float4*)&in[(size_t)(r0 + r) * C + c0 + lx * 4];
        tile[lx * 4 + 0][r] = v.x;
        tile[lx * 4 + 1][r] = v.y;
        tile[lx * 4 + 2][r] = v.z;
        tile[lx * 4 + 3][r] = v.w;
    }
    __syncthreads();
    const int wx = tid & 31;
    const int wy = tid >> 5;
    #pragma unroll
    for (int i = 0; i < 8; i++) {
        const int c = wy + i * 8;
        *(__half2*)&out[(size_t)(c0 + c) * R + r0 + wx * 2] =
            __floats2half2_rn(tile[c][wx * 2], tile[c][wx * 2 + 1]);
    }
}

// ---------------------------------------------------------------------------
// Fused RMSNorm + NeoX RoPE, warp-per-(t,h) — qkv input is fp16 now
// ---------------------------------------------------------------------------
__global__ __launch_bounds__(128)
void normrope_kernel(const __half* __restrict__ qkv,
                     const int*   __restrict__ positions,
                     const float* __restrict__ qw,
                     const float* __restrict__ kw,
                     __half* __restrict__ q_out,
                     __half* __restrict__ k_out,
                     __half* __restrict__ v_out)
{
    const int wg = blockIdx.x * 4 + (threadIdx.x >> 5);
    const int t = wg >> 4, h = wg & 15;
    const int lane = threadIdx.x & 31;
    const int pos = positions[t];
    const size_t row = (size_t)t * QKV_N;
    const size_t obase = (size_t)t * Q_SIZE + h * DH;

    float c[4], sn[4];
    #pragma unroll
    for (int i = 0; i < 4; i++) {
        const float fi = (float)(lane + 32 * i);
        const float fr = expf(-fi * (LN_THETA / 128.0f));
        sincosf((float)pos * fr, &sn[i], &c[i]);
    }

    #pragma unroll
    for (int sec = 0; sec < 3; sec++) {
        const size_t base = row + sec * Q_SIZE + h * DH;
        float x[8];
        #pragma unroll
        for (int i = 0; i < 8; i++) x[i] = __half2float(qkv[base + lane + 32 * i]);
        float ss = 0.0f;
        #pragma unroll
        for (int i = 0; i < 8; i++) ss += x[i] * x[i];
        #pragma unroll
        for (int off = 16; off > 0; off >>= 1) ss += __shfl_xor_sync(0xffffffffu, ss, off);
        const float rs = rsqrtf(ss * (1.0f / DH) + EPS);

        float v[8];
        #pragma unroll
        for (int i = 0; i < 8; i++) {
            float w = 1.0f;
            if (sec == 0) w = qw[lane + 32 * i];
            else if (sec == 1) w = kw[lane + 32 * i];
            v[i] = x[i] * rs * w;
        }
        if (sec < 2) {
            __half* outp = sec == 0 ? q_out : k_out;
            #pragma unroll
            for (int i = 0; i < 4; i++) {
                outp[obase + lane + 32 * i]       = __float2half(v[i] * c[i] - v[i + 4] * sn[i]);
                outp[obase + lane + 32 * i + 128] = __float2half(v[i + 4] * c[i] + v[i] * sn[i]);
            }
        } else {
            #pragma unroll
            for (int i = 0; i < 8; i++)
                v_out[obase + lane + 32 * i] = __float2half(v[i]);
        }
    }
}

// ---------------------------------------------------------------------------
// Launch
// ---------------------------------------------------------------------------
extern "C" void kernel_launch(void* const* d_in, const int* in_sizes, int n_in,
                              void* d_out, int out_size)
{
    const float* hidden    = (const float*)d_in[0];
    const int*   positions = (const int*)  d_in[1];
    const float* w_qkv     = (const float*)d_in[2];
    const float* w_o       = (const float*)d_in[3];
    const float* qw        = (const float*)d_in[4];
    const float* kw        = (const float*)d_in[5];
    float* out = (float*)d_out;

    __half *hid_h, *wqkv_h, *wo_h, *qkv_h, *qh, *kh, *vh, *attn_h;
    cudaGetSymbolAddress((void**)&hid_h,  g_hidden_h);
    cudaGetSymbolAddress((void**)&wqkv_h, g_wqkv_h);
    cudaGetSymbolAddress((void**)&wo_h,   g_wo_h);
    cudaGetSymbolAddress((void**)&qkv_h,  g_qkv_h);
    cudaGetSymbolAddress((void**)&qh,     g_qh);
    cudaGetSymbolAddress((void**)&kh,     g_kh);
    cudaGetSymbolAddress((void**)&vh,     g_vh);
    cudaGetSymbolAddress((void**)&attn_h, g_attn_h);

    cudaFuncSetAttribute(h_gemm<false, false, true >, cudaFuncAttributeMaxDynamicSharedMemorySize, SMEM_BYTES);
    cudaFuncSetAttribute(h_gemm<false, false, false>, cudaFuncAttributeMaxDynamicSharedMemorySize, SMEM_BYTES);
    cudaFuncSetAttribute(flash_kernel, cudaFuncAttributeMaxDynamicSharedMemorySize, FLASH_SMEM);

    // 0) operand conversions / transposes (weights only)
    convert_h_kernel<<<(T_SEQ * HID / 4 + 255) / 256, 256>>>(hidden, hid_h, T_SEQ * HID);
    transpose_f2h<<<dim3(QKV_N / 64, HID / 64), 256>>>(w_qkv, wqkv_h, HID, QKV_N);
    transpose_f2h<<<dim3(HID / 64,   HID / 64), 256>>>(w_o,   wo_h,   HID, HID);

    // 1) qkv = hidden @ w_qkv  (fp16 out)
    h_gemm<false, false, true><<<dim3(QKV_N / BN, T_SEQ / BM, 1), 256, SMEM_BYTES>>>(
        hid_h, wqkv_h, qkv_h, T_SEQ, QKV_N, HID, HID, HID, QKV_N, 0, 0, 0);

    // 2) rmsnorm + rope (fp16 in) -> fp16 q/k/v
    normrope_kernel<<<T_SEQ * NH / 4, 128>>>(qkv_h, positions, qw, kw, qh, kh, vh);

    // 3) fused causal attention: paired q-tiles, balanced single wave
    flash_kernel<<<dim3(T_SEQ / FQM / 2, NH, 1), 256, FLASH_SMEM>>>(qh, kh, vh, attn_h);

    // 4) out = attn @ w_o (fp32 out)
    h_gemm<false, false, false><<<dim3(HID / BN, T_SEQ / BM, 1), 256, SMEM_BYTES>>>(
        attn_h, wo_h, out, T_SEQ, HID, Q_SIZE, Q_SIZE, Q_SIZE, HID, 0, 0, 0);

    (void)in_sizes; (void)n_in; (void)out_size;
}